// round 14
// baseline (speedup 1.0000x reference)
#include <cuda_runtime.h>
#include <cuda_bf16.h>
#include <cstdint>
#include <cstddef>

#define BB   256
#define LL   512
#define EE   256
#define HH   128
#define G4   512
#define TB   8
#define MROWS 131072          // L*B rows per cell
#define WKT  512              // W' width: [hi(256) | lo(256)]

// ---------------------------------------------------------------------------
// Device scratch
// ---------------------------------------------------------------------------
__device__ float g_gx[(size_t)2 * LL * BB * G4];            // 512 MB gates
__device__ __nv_bfloat16 g_wp[(size_t)2 * G4 * WKT];        // 1 MB W' (hi|lo)
__device__ float g_h[(size_t)2 * BB * LL * HH];             // 128 MB hidden states

// ---------------------------------------------------------------------------
// Helpers
// ---------------------------------------------------------------------------
static __device__ __forceinline__ uint32_t smem_u32(const void* p) {
    uint32_t a;
    asm("{ .reg .u64 t; cvta.to.shared.u64 t, %1; cvt.u32.u64 %0, t; }"
        : "=r"(a) : "l"(p));
    return a;
}
static __device__ __forceinline__ void st_remote_b16(uint32_t laddr, uint32_t peer,
                                                     uint16_t v) {
    asm volatile(
        "{ .reg .b32 ra; mapa.shared::cluster.u32 ra, %0, %1; "
        "st.shared::cluster.b16 [ra], %2; }"
        :: "r"(laddr), "r"(peer), "h"(v) : "memory");
}
// fast activations (ex2/rcp approx)
static __device__ __forceinline__ float sigm(float x) {
    float t;
    asm("mul.f32 %0, %1, 0fBFB8AA3B;" : "=f"(t) : "f"(x));   // -x*log2(e)
    asm("ex2.approx.f32 %0, %0;" : "+f"(t));
    float r = t + 1.0f;
    asm("rcp.approx.f32 %0, %0;" : "+f"(r));
    return r;
}
static __device__ __forceinline__ float tanha(float x) {
    x = fminf(fmaxf(x, -9.0f), 9.0f);
    float t;
    asm("mul.f32 %0, %1, 0f4038AA3B;" : "=f"(t) : "f"(x));   // 2x*log2(e)
    asm("ex2.approx.f32 %0, %0;" : "+f"(t));                  // e^{2x}
    float den = t + 1.0f;
    asm("rcp.approx.f32 %0, %0;" : "+f"(den));
    return (t - 1.0f) * den;
}
// cp.async
static __device__ __forceinline__ void cp16(uint32_t dst, const void* src) {
    asm volatile("cp.async.cg.shared.global [%0], [%1], 16;"
                 :: "r"(dst), "l"(src) : "memory");
}
static __device__ __forceinline__ void cp_commit() {
    asm volatile("cp.async.commit_group;" ::: "memory");
}
template <int N>
static __device__ __forceinline__ void cp_wait() {
    asm volatile("cp.async.wait_group %0;" :: "n"(N) : "memory");
}
// ldmatrix x4 (b16)
static __device__ __forceinline__ void ldx4(uint32_t* r, uint32_t addr) {
    asm volatile("ldmatrix.sync.aligned.m8n8.x4.shared.b16 {%0,%1,%2,%3}, [%4];"
                 : "=r"(r[0]), "=r"(r[1]), "=r"(r[2]), "=r"(r[3]) : "r"(addr));
}
// bf16 HMMA m16n8k16, fp32 accum
static __device__ __forceinline__ void mma16816(float* c, const uint32_t* a,
                                                uint32_t b0, uint32_t b1) {
    asm volatile(
        "mma.sync.aligned.m16n8k16.row.col.f32.bf16.bf16.f32 "
        "{%0,%1,%2,%3}, {%4,%5,%6,%7}, {%8,%9}, {%0,%1,%2,%3};"
        : "+f"(c[0]), "+f"(c[1]), "+f"(c[2]), "+f"(c[3])
        : "r"(a[0]), "r"(a[1]), "r"(a[2]), "r"(a[3]), "r"(b0), "r"(b1));
}
static __device__ __forceinline__ uint32_t bfpack(__nv_bfloat16 a, __nv_bfloat16 b) {
    return (uint32_t)__bfloat16_as_ushort(a) | ((uint32_t)__bfloat16_as_ushort(b) << 16);
}

// ---------------------------------------------------------------------------
// W' = [hi | lo]  (512 bf16 per row) — for phase-1 GEMM
// ---------------------------------------------------------------------------
__global__ __launch_bounds__(256) void k_convert_w(const float* __restrict__ Wh,
                                                   const float* __restrict__ Wf) {
    int i = blockIdx.x * 256 + threadIdx.x;
    int e8 = i & 31;
    int nn = i >> 5;
    int cell = nn >> 9;
    int n = nn & 511;
    const float* W = cell ? Wf : Wh;
    const float4* src = reinterpret_cast<const float4*>(W + (size_t)n * EE + e8 * 8);
    float4 v0 = src[0], v1 = src[1];
    float x[8] = {v0.x, v0.y, v0.z, v0.w, v1.x, v1.y, v1.z, v1.w};
    __nv_bfloat16 hi[8], lo[8];
#pragma unroll
    for (int j = 0; j < 8; j++) {
        hi[j] = __float2bfloat16(x[j]);
        lo[j] = __float2bfloat16(x[j] - __bfloat162float(hi[j]));
    }
    uint4 ph, pl;
    ph.x = bfpack(hi[0], hi[1]); ph.y = bfpack(hi[2], hi[3]);
    ph.z = bfpack(hi[4], hi[5]); ph.w = bfpack(hi[6], hi[7]);
    pl.x = bfpack(lo[0], lo[1]); pl.y = bfpack(lo[2], lo[3]);
    pl.z = bfpack(lo[4], lo[5]); pl.w = bfpack(lo[6], lo[7]);
    __nv_bfloat16* dst = g_wp + (size_t)nn * WKT + e8 * 8;
    *reinterpret_cast<uint4*>(dst)       = ph;
    *reinterpret_cast<uint4*>(dst + 256) = pl;
}

// ---------------------------------------------------------------------------
// Phase 1 fused GEMM — EXACT R11 version (M64 x N256, 256 thr, 2 CTAs/SM).
// ---------------------------------------------------------------------------
#define OFF_B   20480
#define OFF_BIAS 102400
#define SMEM_P1 (102400 + 1024)

__global__ __launch_bounds__(256, 2) void k_mma_gemm(
    const float* __restrict__ Xh, const float* __restrict__ Xf,
    const float* __restrict__ bih_h, const float* __restrict__ bhh_h,
    const float* __restrict__ bih_f, const float* __restrict__ bhh_f)
{
    extern __shared__ __align__(16) char smem[];
    const uint32_t sbase = smem_u32(smem);
    float* bias_s = reinterpret_cast<float*>(smem + OFF_BIAS);

    const int tid  = threadIdx.x;
    const int wid  = tid >> 5;
    const int lane = tid & 31;
    const int n0 = blockIdx.x * 256;
    const int m0 = blockIdx.y * 64;
    const int cell = m0 >> 17;

    {
        const float* bi = cell ? bih_f : bih_h;
        const float* bh = cell ? bhh_f : bhh_h;
        bias_s[tid] = bi[n0 + tid] + bh[n0 + tid];
    }

    const float* X = cell ? Xf : Xh;

    const int arow = tid >> 2;
    const int aq   = (tid & 3) * 8;
    const int rA = (m0 + arow) & (MROWS - 1);
    const float* xsrc = X + (((size_t)(rA & 255)) * LL + (rA >> 8)) * EE + aq;
    const uint32_t a_sts_h = sbase + arow * 80 + aq * 2;
    const uint32_t a_sts_l = a_sts_h + 5120;

    const int warp_m = wid & 1;
    const int warp_n = wid >> 1;
    uint32_t a_off[2];
#pragma unroll
    for (int im = 0; im < 2; im++)
        a_off[im] = (warp_m * 32 + im * 16 + (lane & 15)) * 80 + (lane >> 4) * 16;
    uint32_t b_off[4];
#pragma unroll
    for (int ip = 0; ip < 4; ip++)
        b_off[ip] = (warp_n * 64 + ip * 16 + (lane >> 4) * 8 + (lane & 7)) * 80
                  + ((lane >> 3) & 1) * 16;

    float acc[2][8][4];
#pragma unroll
    for (int im = 0; im < 2; im++)
#pragma unroll
        for (int in = 0; in < 8; in++)
#pragma unroll
            for (int q = 0; q < 4; q++) acc[im][in][q] = 0.0f;

#define LOAD_B(chunk)                                                          \
    do {                                                                       \
        const int _k0 = (chunk) * 32;                                          \
        const uint32_t _bb = sbase + OFF_B + (uint32_t)((chunk) & 1) * 40960;  \
        _Pragma("unroll")                                                      \
        for (int _i = 0; _i < 8; _i++) {                                       \
            int _idx = tid + _i * 256;                                         \
            int _half = _idx >> 10;                                            \
            int _r2 = _idx & 1023;                                             \
            int _brow = _r2 >> 2;                                              \
            int _pc = _r2 & 3;                                                 \
            cp16(_bb + _half * 20480 + _brow * 80 + _pc * 16,                  \
                 g_wp + ((size_t)cell * G4 + n0 + _brow) * WKT                 \
                      + _half * 256 + _k0 + _pc * 8);                          \
        }                                                                      \
        cp_commit();                                                           \
    } while (0)

    float4 xr0 = reinterpret_cast<const float4*>(xsrc)[0];
    float4 xr1 = reinterpret_cast<const float4*>(xsrc)[1];
    LOAD_B(0);

    for (int k = 0; k < 8; ++k) {
        const uint32_t aboff = (uint32_t)(k & 1) * 10240;
        const uint32_t bboff = (uint32_t)(k & 1) * 40960;

        {
            float x8[8] = {xr0.x, xr0.y, xr0.z, xr0.w, xr1.x, xr1.y, xr1.z, xr1.w};
            __nv_bfloat16 hi[8], lo[8];
#pragma unroll
            for (int j = 0; j < 8; j++) {
                hi[j] = __float2bfloat16(x8[j]);
                lo[j] = __float2bfloat16(x8[j] - __bfloat162float(hi[j]));
            }
            uint4 ph, pl;
            ph.x = bfpack(hi[0], hi[1]); ph.y = bfpack(hi[2], hi[3]);
            ph.z = bfpack(hi[4], hi[5]); ph.w = bfpack(hi[6], hi[7]);
            pl.x = bfpack(lo[0], lo[1]); pl.y = bfpack(lo[2], lo[3]);
            pl.z = bfpack(lo[4], lo[5]); pl.w = bfpack(lo[6], lo[7]);
            asm volatile("st.shared.v4.b32 [%0], {%1,%2,%3,%4};"
                         :: "r"(a_sts_h + aboff), "r"(ph.x), "r"(ph.y), "r"(ph.z), "r"(ph.w)
                         : "memory");
            asm volatile("st.shared.v4.b32 [%0], {%1,%2,%3,%4};"
                         :: "r"(a_sts_l + aboff), "r"(pl.x), "r"(pl.y), "r"(pl.z), "r"(pl.w)
                         : "memory");
        }
        if (k < 7) {
            xr0 = reinterpret_cast<const float4*>(xsrc + (k + 1) * 32)[0];
            xr1 = reinterpret_cast<const float4*>(xsrc + (k + 1) * 32)[1];
        }
        cp_wait<0>();
        __syncthreads();
        if (k < 7) LOAD_B(k + 1);

#pragma unroll
        for (int ks = 0; ks < 2; ks++) {
            const uint32_t kb = ks * 32;
            uint32_t ahi[2][4], bfr[16];
            ldx4(ahi[0], sbase + aboff + a_off[0] + kb);
            ldx4(ahi[1], sbase + aboff + a_off[1] + kb);
#pragma unroll
            for (int ip = 0; ip < 4; ip++)
                ldx4(bfr + ip * 4, sbase + OFF_B + bboff + b_off[ip] + kb);
#pragma unroll
            for (int im = 0; im < 2; im++)
#pragma unroll
                for (int in = 0; in < 8; in++)
                    mma16816(acc[im][in], ahi[im], bfr[in * 2], bfr[in * 2 + 1]);
            {
                uint32_t alo[2][4];
                ldx4(alo[0], sbase + aboff + 5120 + a_off[0] + kb);
                ldx4(alo[1], sbase + aboff + 5120 + a_off[1] + kb);
#pragma unroll
                for (int im = 0; im < 2; im++)
#pragma unroll
                    for (int in = 0; in < 8; in++)
                        mma16816(acc[im][in], alo[im], bfr[in * 2], bfr[in * 2 + 1]);
            }
#pragma unroll
            for (int ip = 0; ip < 4; ip++)
                ldx4(bfr + ip * 4, sbase + OFF_B + bboff + 20480 + b_off[ip] + kb);
#pragma unroll
            for (int im = 0; im < 2; im++)
#pragma unroll
                for (int in = 0; in < 8; in++)
                    mma16816(acc[im][in], ahi[im], bfr[in * 2], bfr[in * 2 + 1]);
        }
    }
    __syncthreads();

#pragma unroll
    for (int im = 0; im < 2; im++) {
#pragma unroll
        for (int h = 0; h < 2; h++) {
            int m = m0 + warp_m * 32 + im * 16 + h * 8 + (lane >> 2);
            int r = m & (MROWS - 1);
            int t = r >> 8, b = r & 255;
            float* gp = g_gx + (((size_t)cell * LL + t) * BB + b) * G4 + n0;
#pragma unroll
            for (int in = 0; in < 8; in++) {
                int col = warp_n * 64 + in * 8 + (lane & 3) * 2;
                float2 v;
                v.x = acc[im][in][2 * h + 0] + bias_s[col];
                v.y = acc[im][in][2 * h + 1] + bias_s[col + 1];
                *reinterpret_cast<float2*>(gp + col) = v;
            }
        }
    }
}

// ---------------------------------------------------------------------------
// Phase 2: recurrent LSTM — R11 structure with ONE change: the 24-HMMA
// serial accumulator chain is split into 3 independent accumulators
// (one per hi/lo product), summed at the end. Everything else identical.
// ---------------------------------------------------------------------------
__global__ __launch_bounds__(256, 2) __cluster_dims__(4, 1, 1)
void k_recurrent(const float* __restrict__ Whh_h,
                 const float* __restrict__ Whh_f)
{
    __shared__ uint32_t hp_hi[2][TB][68];    // [buf][batch][k-pair] bf16x2
    __shared__ uint32_t hp_lo[2][TB][68];
    __shared__ float gates_s[128][10];

    const int tid = threadIdx.x;
    uint32_t rank;
    asm("mov.u32 %0, %%cluster_ctarank;" : "=r"(rank));
    const int q    = blockIdx.x >> 2;
    const int cell = q >> 5;
    const int b0   = (q & 31) * TB;

    const float* W = cell ? Whh_f : Whh_h;

    const int w    = tid >> 5;
    const int lane = tid & 31;
    const int gid  = lane >> 2;             // 0..7
    const int tig  = lane & 3;              // 0..3

    const int rloc0 = w * 16 + gid;
    const int rloc1 = rloc0 + 8;
    const int ng0 = (rloc0 >> 5) * HH + (int)rank * 32 + (rloc0 & 31);
    const int ng1 = (rloc1 >> 5) * HH + (int)rank * 32 + (rloc1 & 31);

    uint32_t a_hi[8][4], a_lo[8][4];
#pragma unroll
    for (int kt = 0; kt < 8; kt++) {
        int c0 = kt * 16 + 2 * tig;
#pragma unroll
        for (int rr = 0; rr < 2; rr++) {
            const float* wr = W + (size_t)(rr ? ng1 : ng0) * HH;
#pragma unroll
            for (int cc = 0; cc < 2; cc++) {
                float xa = wr[c0 + cc * 8];
                float xb = wr[c0 + cc * 8 + 1];
                __nv_bfloat16 ha = __float2bfloat16(xa);
                __nv_bfloat16 hb = __float2bfloat16(xb);
                __nv_bfloat16 la = __float2bfloat16(xa - __bfloat162float(ha));
                __nv_bfloat16 lb = __float2bfloat16(xb - __bfloat162float(hb));
                a_hi[kt][cc * 2 + rr] = bfpack(ha, hb);
                a_lo[kt][cc * 2 + rr] = bfpack(la, lb);
            }
        }
    }

    const int pb = tid >> 5;
    const int pj = tid & 31;
    const int jglob = (int)rank * 32 + pj;
    const uint32_t hhi_u16_0 = smem_u32(&hp_hi[0][0][0]) + (pb * 136 + jglob) * 2;
    const uint32_t hhi_u16_1 = smem_u32(&hp_hi[1][0][0]) + (pb * 136 + jglob) * 2;
    const uint32_t hlo_u16_0 = smem_u32(&hp_lo[0][0][0]) + (pb * 136 + jglob) * 2;
    const uint32_t hlo_u16_1 = smem_u32(&hp_lo[1][0][0]) + (pb * 136 + jglob) * 2;
    float* hg = g_h + (((size_t)cell * BB + b0 + pb) * LL) * HH + jglob;

    for (int i = tid; i < 2 * TB * 68; i += 256) {
        (&hp_hi[0][0][0])[i] = 0u;
        (&hp_lo[0][0][0])[i] = 0u;
    }
    float c_reg = 0.0f;
    __syncthreads();
    asm volatile("barrier.cluster.arrive.aligned;" ::: "memory");
    asm volatile("barrier.cluster.wait.aligned;"   ::: "memory");

    const float* gxbase = g_gx + ((size_t)cell * LL * BB + (b0 + pb)) * G4 + jglob;
    float gxr[4];
#pragma unroll
    for (int gi = 0; gi < 4; gi++)
        gxr[gi] = gxbase[gi * HH];

    const uint32_t* hhi_base = &hp_hi[0][0][0];
    const uint32_t* hlo_base = &hp_lo[0][0][0];

    int buf = 0;
    for (int t = 0; t < LL; t++) {
        // ---- gates via tensor pipe: 3 independent accumulator chains
        float c0a[4] = {0.0f, 0.0f, 0.0f, 0.0f};
        float c1a[4] = {0.0f, 0.0f, 0.0f, 0.0f};
        float c2a[4] = {0.0f, 0.0f, 0.0f, 0.0f};
        const int fb = buf * TB * 68 + gid * 68;
#pragma unroll
        for (int kt = 0; kt < 8; kt++) {
            int pidx = fb + kt * 8 + tig;
            uint32_t bh0 = hhi_base[pidx];
            uint32_t bh1 = hhi_base[pidx + 4];
            uint32_t bl0 = hlo_base[pidx];
            uint32_t bl1 = hlo_base[pidx + 4];
            mma16816(c0a, a_hi[kt], bh0, bh1);
            mma16816(c1a, a_hi[kt], bl0, bl1);
            mma16816(c2a, a_lo[kt], bh0, bh1);
        }
        float cfr[4];
#pragma unroll
        for (int qq = 0; qq < 4; qq++)
            cfr[qq] = (c0a[qq] + c1a[qq]) + c2a[qq];

        *reinterpret_cast<float2*>(&gates_s[rloc0][2 * tig]) =
            make_float2(cfr[0], cfr[1]);
        *reinterpret_cast<float2*>(&gates_s[rloc1][2 * tig]) =
            make_float2(cfr[2], cfr[3]);
        __syncthreads();

        float gi_ = gates_s[pj][pb]       + gxr[0];
        float gf_ = gates_s[32 + pj][pb]  + gxr[1];
        float gg_ = gates_s[64 + pj][pb]  + gxr[2];
        float go_ = gates_s[96 + pj][pb]  + gxr[3];
        float ig = sigm(gi_);
        float fg = sigm(gf_);
        float gv = tanha(gg_);
        float og = sigm(go_);
        c_reg = fg * c_reg + ig * gv;
        float hv = og * tanha(c_reg);

        __nv_bfloat16 hhi = __float2bfloat16(hv);
        __nv_bfloat16 hlo = __float2bfloat16(hv - __bfloat162float(hhi));
        uint16_t hhi_b = __bfloat16_as_ushort(hhi);
        uint16_t hlo_b = __bfloat16_as_ushort(hlo);

        const int nb = buf ^ 1;
        const uint32_t ahh = nb ? hhi_u16_1 : hhi_u16_0;
        const uint32_t ahl = nb ? hlo_u16_1 : hlo_u16_0;
        asm volatile("st.shared.b16 [%0], %1;" :: "r"(ahh), "h"(hhi_b) : "memory");
        asm volatile("st.shared.b16 [%0], %1;" :: "r"(ahl), "h"(hlo_b) : "memory");
#pragma unroll
        for (int r = 1; r < 4; r++) {
            st_remote_b16(ahh, (rank + r) & 3u, hhi_b);
            st_remote_b16(ahl, (rank + r) & 3u, hlo_b);
        }
        hg[(size_t)t * HH] = hv;

        if (t + 1 < LL) {
            const float* gp = gxbase + (size_t)(t + 1) * BB * G4;
#pragma unroll
            for (int gi2 = 0; gi2 < 4; gi2++)
                gxr[gi2] = gp[gi2 * HH];
        }

        asm volatile("barrier.cluster.arrive.aligned;" ::: "memory");
        asm volatile("barrier.cluster.wait.aligned;"   ::: "memory");
        buf = nb;
    }
}

// ---------------------------------------------------------------------------
// Phase 3: y[b][t] = W_ffn . [h_h(b,t); h_f(b,t)] + b_ffn  (R9 version)
// ---------------------------------------------------------------------------
__global__ __launch_bounds__(256) void k_finalize(float* __restrict__ out,
                                                  const float* __restrict__ Wffn,
                                                  const float* __restrict__ bffn) {
    __shared__ float wf[2 * HH];
    const int b = blockIdx.x >> 1;
    const int t = (blockIdx.x & 1) * 256 + threadIdx.x;
    wf[threadIdx.x] = Wffn[threadIdx.x];
    __syncthreads();
    const float bias = bffn[0];

    const float4* p0 = reinterpret_cast<const float4*>(
        g_h + (((size_t)0 * BB + b) * LL + t) * HH);
    const float4* p1 = reinterpret_cast<const float4*>(
        g_h + (((size_t)1 * BB + b) * LL + t) * HH);
    float acc = bias;
#pragma unroll 8
    for (int q = 0; q < 32; q++) {
        float4 a = p0[q];
        acc += a.x * wf[4 * q] + a.y * wf[4 * q + 1]
             + a.z * wf[4 * q + 2] + a.w * wf[4 * q + 3];
    }
#pragma unroll 8
    for (int q = 0; q < 32; q++) {
        float4 a = p1[q];
        acc += a.x * wf[128 + 4 * q] + a.y * wf[128 + 4 * q + 1]
             + a.z * wf[128 + 4 * q + 2] + a.w * wf[128 + 4 * q + 3];
    }
    out[(size_t)b * LL + t] = acc;
}

// ---------------------------------------------------------------------------
extern "C" void kernel_launch(void* const* d_in, const int* in_sizes, int n_in,
                              void* d_out, int out_size) {
    const float* hist  = (const float*)d_in[0];
    const float* fut   = (const float*)d_in[1];
    const float* Wih_h = (const float*)d_in[2];
    const float* Whh_h = (const float*)d_in[3];
    const float* bih_h = (const float*)d_in[4];
    const float* bhh_h = (const float*)d_in[5];
    const float* Wih_f = (const float*)d_in[6];
    const float* Whh_f = (const float*)d_in[7];
    const float* bih_f = (const float*)d_in[8];
    const float* bhh_f = (const float*)d_in[9];
    const float* Wffn  = (const float*)d_in[10];
    const float* bffn  = (const float*)d_in[11];
    float* out = (float*)d_out;

    static int smem_set = 0;
    if (!smem_set) {
        cudaFuncSetAttribute(k_mma_gemm,
                             cudaFuncAttributeMaxDynamicSharedMemorySize, SMEM_P1);
        smem_set = 1;
    }

    k_convert_w<<<(2 * G4 * 32) / 256, 256>>>(Wih_h, Wih_f);

    dim3 gg(G4 / 256, (2 * MROWS) / 64);   // (2, 4096)
    k_mma_gemm<<<gg, 256, SMEM_P1>>>(hist, fut, bih_h, bhh_h, bih_f, bhh_f);

    k_recurrent<<<256, 256>>>(Whh_h, Whh_f);

    k_finalize<<<2 * BB, 256>>>(out, Wffn, bffn);
}

// round 15
// speedup vs baseline: 1.0339x; 1.0339x over previous
#include <cuda_runtime.h>
#include <cuda_bf16.h>
#include <cstdint>
#include <cstddef>

#define BB   256
#define LL   512
#define EE   256
#define HH   128
#define G4   512
#define TB   8
#define MROWS 131072          // L*B rows per cell
#define WKT  512              // W' width: [hi(256) | lo(256)]

// ---------------------------------------------------------------------------
// Device scratch
// ---------------------------------------------------------------------------
__device__ float g_gx[(size_t)2 * LL * BB * G4];            // 512 MB gates
__device__ __nv_bfloat16 g_wp[(size_t)2 * G4 * WKT];        // 1 MB W' (hi|lo)
__device__ float g_h[(size_t)2 * BB * LL * HH];             // 128 MB hidden states

// ---------------------------------------------------------------------------
// Helpers
// ---------------------------------------------------------------------------
static __device__ __forceinline__ uint32_t smem_u32(const void* p) {
    uint32_t a;
    asm("{ .reg .u64 t; cvta.to.shared.u64 t, %1; cvt.u32.u64 %0, t; }"
        : "=r"(a) : "l"(p));
    return a;
}
static __device__ __forceinline__ void st_remote_b16(uint32_t laddr, uint32_t peer,
                                                     uint16_t v) {
    asm volatile(
        "{ .reg .b32 ra; mapa.shared::cluster.u32 ra, %0, %1; "
        "st.shared::cluster.b16 [ra], %2; }"
        :: "r"(laddr), "r"(peer), "h"(v) : "memory");
}
// fast activations (ex2/rcp approx)
static __device__ __forceinline__ float sigm(float x) {
    float t;
    asm("mul.f32 %0, %1, 0fBFB8AA3B;" : "=f"(t) : "f"(x));   // -x*log2(e)
    asm("ex2.approx.f32 %0, %0;" : "+f"(t));
    float r = t + 1.0f;
    asm("rcp.approx.f32 %0, %0;" : "+f"(r));
    return r;
}
static __device__ __forceinline__ float tanha(float x) {
    x = fminf(fmaxf(x, -9.0f), 9.0f);
    float t;
    asm("mul.f32 %0, %1, 0f4038AA3B;" : "=f"(t) : "f"(x));   // 2x*log2(e)
    asm("ex2.approx.f32 %0, %0;" : "+f"(t));                  // e^{2x}
    float den = t + 1.0f;
    asm("rcp.approx.f32 %0, %0;" : "+f"(den));
    return (t - 1.0f) * den;
}
// cp.async
static __device__ __forceinline__ void cp16(uint32_t dst, const void* src) {
    asm volatile("cp.async.cg.shared.global [%0], [%1], 16;"
                 :: "r"(dst), "l"(src) : "memory");
}
static __device__ __forceinline__ void cp_commit() {
    asm volatile("cp.async.commit_group;" ::: "memory");
}
template <int N>
static __device__ __forceinline__ void cp_wait() {
    asm volatile("cp.async.wait_group %0;" :: "n"(N) : "memory");
}
// ldmatrix x4 (b16)
static __device__ __forceinline__ void ldx4(uint32_t* r, uint32_t addr) {
    asm volatile("ldmatrix.sync.aligned.m8n8.x4.shared.b16 {%0,%1,%2,%3}, [%4];"
                 : "=r"(r[0]), "=r"(r[1]), "=r"(r[2]), "=r"(r[3]) : "r"(addr));
}
// bf16 HMMA m16n8k16, fp32 accum
static __device__ __forceinline__ void mma16816(float* c, const uint32_t* a,
                                                uint32_t b0, uint32_t b1) {
    asm volatile(
        "mma.sync.aligned.m16n8k16.row.col.f32.bf16.bf16.f32 "
        "{%0,%1,%2,%3}, {%4,%5,%6,%7}, {%8,%9}, {%0,%1,%2,%3};"
        : "+f"(c[0]), "+f"(c[1]), "+f"(c[2]), "+f"(c[3])
        : "r"(a[0]), "r"(a[1]), "r"(a[2]), "r"(a[3]), "r"(b0), "r"(b1));
}
static __device__ __forceinline__ uint32_t bfpack(__nv_bfloat16 a, __nv_bfloat16 b) {
    return (uint32_t)__bfloat16_as_ushort(a) | ((uint32_t)__bfloat16_as_ushort(b) << 16);
}

// ---------------------------------------------------------------------------
// W' = [hi | lo]  (512 bf16 per row) — for phase-1 GEMM
// ---------------------------------------------------------------------------
__global__ __launch_bounds__(256) void k_convert_w(const float* __restrict__ Wh,
                                                   const float* __restrict__ Wf) {
    int i = blockIdx.x * 256 + threadIdx.x;
    int e8 = i & 31;
    int nn = i >> 5;
    int cell = nn >> 9;
    int n = nn & 511;
    const float* W = cell ? Wf : Wh;
    const float4* src = reinterpret_cast<const float4*>(W + (size_t)n * EE + e8 * 8);
    float4 v0 = src[0], v1 = src[1];
    float x[8] = {v0.x, v0.y, v0.z, v0.w, v1.x, v1.y, v1.z, v1.w};
    __nv_bfloat16 hi[8], lo[8];
#pragma unroll
    for (int j = 0; j < 8; j++) {
        hi[j] = __float2bfloat16(x[j]);
        lo[j] = __float2bfloat16(x[j] - __bfloat162float(hi[j]));
    }
    uint4 ph, pl;
    ph.x = bfpack(hi[0], hi[1]); ph.y = bfpack(hi[2], hi[3]);
    ph.z = bfpack(hi[4], hi[5]); ph.w = bfpack(hi[6], hi[7]);
    pl.x = bfpack(lo[0], lo[1]); pl.y = bfpack(lo[2], lo[3]);
    pl.z = bfpack(lo[4], lo[5]); pl.w = bfpack(lo[6], lo[7]);
    __nv_bfloat16* dst = g_wp + (size_t)nn * WKT + e8 * 8;
    *reinterpret_cast<uint4*>(dst)       = ph;
    *reinterpret_cast<uint4*>(dst + 256) = pl;
}

// ---------------------------------------------------------------------------
// Phase 1 fused GEMM v3: R11 tiling (M64 x N256, 256 thr, 2 CTAs/SM) with
// software-pipelined A-conversion: convert+STS for chunk k+1 happens AFTER
// issuing chunk k's MMAs (tensor pipe crunches while ALU converts).
// ---------------------------------------------------------------------------
#define OFF_B   20480
#define OFF_BIAS 102400
#define SMEM_P1 (102400 + 1024)

__global__ __launch_bounds__(256, 2) void k_mma_gemm(
    const float* __restrict__ Xh, const float* __restrict__ Xf,
    const float* __restrict__ bih_h, const float* __restrict__ bhh_h,
    const float* __restrict__ bih_f, const float* __restrict__ bhh_f)
{
    extern __shared__ __align__(16) char smem[];
    const uint32_t sbase = smem_u32(smem);
    float* bias_s = reinterpret_cast<float*>(smem + OFF_BIAS);

    const int tid  = threadIdx.x;
    const int wid  = tid >> 5;
    const int lane = tid & 31;
    const int n0 = blockIdx.x * 256;
    const int m0 = blockIdx.y * 64;
    const int cell = m0 >> 17;

    {
        const float* bi = cell ? bih_f : bih_h;
        const float* bh = cell ? bhh_f : bhh_h;
        bias_s[tid] = bi[n0 + tid] + bh[n0 + tid];
    }

    const float* X = cell ? Xf : Xh;

    const int arow = tid >> 2;
    const int aq   = (tid & 3) * 8;
    const int rA = (m0 + arow) & (MROWS - 1);
    const float* xsrc = X + (((size_t)(rA & 255)) * LL + (rA >> 8)) * EE + aq;
    const uint32_t a_sts_h = sbase + arow * 80 + aq * 2;          // + buf*10240
    const uint32_t a_sts_l = a_sts_h + 5120;

    const int warp_m = wid & 1;
    const int warp_n = wid >> 1;
    uint32_t a_off[2];
#pragma unroll
    for (int im = 0; im < 2; im++)
        a_off[im] = (warp_m * 32 + im * 16 + (lane & 15)) * 80 + (lane >> 4) * 16;
    uint32_t b_off[4];
#pragma unroll
    for (int ip = 0; ip < 4; ip++)
        b_off[ip] = (warp_n * 64 + ip * 16 + (lane >> 4) * 8 + (lane & 7)) * 80
                  + ((lane >> 3) & 1) * 16;

    float acc[2][8][4];
#pragma unroll
    for (int im = 0; im < 2; im++)
#pragma unroll
        for (int in = 0; in < 8; in++)
#pragma unroll
            for (int q = 0; q < 4; q++) acc[im][in][q] = 0.0f;

#define LOAD_B(chunk)                                                          \
    do {                                                                       \
        const int _k0 = (chunk) * 32;                                          \
        const uint32_t _bb = sbase + OFF_B + (uint32_t)((chunk) & 1) * 40960;  \
        _Pragma("unroll")                                                      \
        for (int _i = 0; _i < 8; _i++) {                                       \
            int _idx = tid + _i * 256;                                         \
            int _half = _idx >> 10;                                            \
            int _r2 = _idx & 1023;                                             \
            int _brow = _r2 >> 2;                                              \
            int _pc = _r2 & 3;                                                 \
            cp16(_bb + _half * 20480 + _brow * 80 + _pc * 16,                  \
                 g_wp + ((size_t)cell * G4 + n0 + _brow) * WKT                 \
                      + _half * 256 + _k0 + _pc * 8);                          \
        }                                                                      \
        cp_commit();                                                           \
    } while (0)

#define CONVERT_STS(dstoff)                                                    \
    do {                                                                       \
        float x8[8] = {xr0.x, xr0.y, xr0.z, xr0.w, xr1.x, xr1.y, xr1.z, xr1.w};\
        __nv_bfloat16 hi[8], lo[8];                                            \
        _Pragma("unroll")                                                      \
        for (int _j = 0; _j < 8; _j++) {                                       \
            hi[_j] = __float2bfloat16(x8[_j]);                                 \
            lo[_j] = __float2bfloat16(x8[_j] - __bfloat162float(hi[_j]));      \
        }                                                                      \
        uint4 ph, pl;                                                          \
        ph.x = bfpack(hi[0], hi[1]); ph.y = bfpack(hi[2], hi[3]);              \
        ph.z = bfpack(hi[4], hi[5]); ph.w = bfpack(hi[6], hi[7]);              \
        pl.x = bfpack(lo[0], lo[1]); pl.y = bfpack(lo[2], lo[3]);              \
        pl.z = bfpack(lo[4], lo[5]); pl.w = bfpack(lo[6], lo[7]);              \
        asm volatile("st.shared.v4.b32 [%0], {%1,%2,%3,%4};"                   \
                     :: "r"(a_sts_h + (dstoff)), "r"(ph.x), "r"(ph.y),         \
                        "r"(ph.z), "r"(ph.w) : "memory");                      \
        asm volatile("st.shared.v4.b32 [%0], {%1,%2,%3,%4};"                   \
                     :: "r"(a_sts_l + (dstoff)), "r"(pl.x), "r"(pl.y),         \
                        "r"(pl.z), "r"(pl.w) : "memory");                      \
    } while (0)

    // ---- prologue: chunk 0 converted+stored; chunk 1 in regs; B(0) landed
    float4 xr0 = reinterpret_cast<const float4*>(xsrc)[0];
    float4 xr1 = reinterpret_cast<const float4*>(xsrc)[1];
    LOAD_B(0);
    CONVERT_STS(0u);
    xr0 = reinterpret_cast<const float4*>(xsrc + 32)[0];
    xr1 = reinterpret_cast<const float4*>(xsrc + 32)[1];
    cp_wait<0>();
    __syncthreads();

    for (int k = 0; k < 8; ++k) {
        const uint32_t aboff = (uint32_t)(k & 1) * 10240;
        const uint32_t bboff = (uint32_t)(k & 1) * 40960;

        // commit next B early (lands during this chunk's MMA)
        if (k < 7) LOAD_B(k + 1);

        // ---- MMA chunk k: 2 K16 slices x 3 products
#pragma unroll
        for (int ks = 0; ks < 2; ks++) {
            const uint32_t kb = ks * 32;
            uint32_t ahi[2][4], bfr[16];
            ldx4(ahi[0], sbase + aboff + a_off[0] + kb);
            ldx4(ahi[1], sbase + aboff + a_off[1] + kb);
#pragma unroll
            for (int ip = 0; ip < 4; ip++)
                ldx4(bfr + ip * 4, sbase + OFF_B + bboff + b_off[ip] + kb);
#pragma unroll
            for (int im = 0; im < 2; im++)
#pragma unroll
                for (int in = 0; in < 8; in++)
                    mma16816(acc[im][in], ahi[im], bfr[in * 2], bfr[in * 2 + 1]);
            {
                uint32_t alo[2][4];
                ldx4(alo[0], sbase + aboff + 5120 + a_off[0] + kb);
                ldx4(alo[1], sbase + aboff + 5120 + a_off[1] + kb);
#pragma unroll
                for (int im = 0; im < 2; im++)
#pragma unroll
                    for (int in = 0; in < 8; in++)
                        mma16816(acc[im][in], alo[im], bfr[in * 2], bfr[in * 2 + 1]);
            }
#pragma unroll
            for (int ip = 0; ip < 4; ip++)
                ldx4(bfr + ip * 4, sbase + OFF_B + bboff + 20480 + b_off[ip] + kb);
#pragma unroll
            for (int im = 0; im < 2; im++)
#pragma unroll
                for (int in = 0; in < 8; in++)
                    mma16816(acc[im][in], ahi[im], bfr[in * 2], bfr[in * 2 + 1]);
        }

        // ---- pipelined A-conversion for chunk k+1 (overlaps tensor work)
        if (k < 7) {
            CONVERT_STS((uint32_t)((k + 1) & 1) * 10240);
            if (k < 6) {
                xr0 = reinterpret_cast<const float4*>(xsrc + (k + 2) * 32)[0];
                xr1 = reinterpret_cast<const float4*>(xsrc + (k + 2) * 32)[1];
            }
            cp_wait<0>();
        }
        __syncthreads();
    }

    // ---- epilogue: fp32 + bias -> g_gx
#pragma unroll
    for (int im = 0; im < 2; im++) {
#pragma unroll
        for (int h = 0; h < 2; h++) {
            int m = m0 + warp_m * 32 + im * 16 + h * 8 + (lane >> 2);
            int r = m & (MROWS - 1);
            int t = r >> 8, b = r & 255;
            float* gp = g_gx + (((size_t)cell * LL + t) * BB + b) * G4 + n0;
#pragma unroll
            for (int in = 0; in < 8; in++) {
                int col = warp_n * 64 + in * 8 + (lane & 3) * 2;
                float2 v;
                v.x = acc[im][in][2 * h + 0] + bias_s[col];
                v.y = acc[im][in][2 * h + 1] + bias_s[col + 1];
                *reinterpret_cast<float2*>(gp + col) = v;
            }
        }
    }
}

// ---------------------------------------------------------------------------
// Phase 2: recurrent LSTM — EXACT R11 version (measured best 1472.8 us).
// Single cfr accumulator. DO NOT TOUCH.
// ---------------------------------------------------------------------------
__global__ __launch_bounds__(256, 2) __cluster_dims__(4, 1, 1)
void k_recurrent(const float* __restrict__ Whh_h,
                 const float* __restrict__ Whh_f)
{
    __shared__ uint32_t hp_hi[2][TB][68];    // [buf][batch][k-pair] bf16x2
    __shared__ uint32_t hp_lo[2][TB][68];
    __shared__ float gates_s[128][10];

    const int tid = threadIdx.x;
    uint32_t rank;
    asm("mov.u32 %0, %%cluster_ctarank;" : "=r"(rank));
    const int q    = blockIdx.x >> 2;
    const int cell = q >> 5;
    const int b0   = (q & 31) * TB;

    const float* W = cell ? Whh_f : Whh_h;

    const int w    = tid >> 5;
    const int lane = tid & 31;
    const int gid  = lane >> 2;             // 0..7
    const int tig  = lane & 3;              // 0..3

    const int rloc0 = w * 16 + gid;
    const int rloc1 = rloc0 + 8;
    const int ng0 = (rloc0 >> 5) * HH + (int)rank * 32 + (rloc0 & 31);
    const int ng1 = (rloc1 >> 5) * HH + (int)rank * 32 + (rloc1 & 31);

    uint32_t a_hi[8][4], a_lo[8][4];
#pragma unroll
    for (int kt = 0; kt < 8; kt++) {
        int c0 = kt * 16 + 2 * tig;
#pragma unroll
        for (int rr = 0; rr < 2; rr++) {
            const float* wr = W + (size_t)(rr ? ng1 : ng0) * HH;
#pragma unroll
            for (int cc = 0; cc < 2; cc++) {
                float xa = wr[c0 + cc * 8];
                float xb = wr[c0 + cc * 8 + 1];
                __nv_bfloat16 ha = __float2bfloat16(xa);
                __nv_bfloat16 hb = __float2bfloat16(xb);
                __nv_bfloat16 la = __float2bfloat16(xa - __bfloat162float(ha));
                __nv_bfloat16 lb = __float2bfloat16(xb - __bfloat162float(hb));
                a_hi[kt][cc * 2 + rr] = bfpack(ha, hb);
                a_lo[kt][cc * 2 + rr] = bfpack(la, lb);
            }
        }
    }

    const int pb = tid >> 5;
    const int pj = tid & 31;
    const int jglob = (int)rank * 32 + pj;
    const uint32_t hhi_u16_0 = smem_u32(&hp_hi[0][0][0]) + (pb * 136 + jglob) * 2;
    const uint32_t hhi_u16_1 = smem_u32(&hp_hi[1][0][0]) + (pb * 136 + jglob) * 2;
    const uint32_t hlo_u16_0 = smem_u32(&hp_lo[0][0][0]) + (pb * 136 + jglob) * 2;
    const uint32_t hlo_u16_1 = smem_u32(&hp_lo[1][0][0]) + (pb * 136 + jglob) * 2;
    float* hg = g_h + (((size_t)cell * BB + b0 + pb) * LL) * HH + jglob;

    for (int i = tid; i < 2 * TB * 68; i += 256) {
        (&hp_hi[0][0][0])[i] = 0u;
        (&hp_lo[0][0][0])[i] = 0u;
    }
    float c_reg = 0.0f;
    __syncthreads();
    asm volatile("barrier.cluster.arrive.aligned;" ::: "memory");
    asm volatile("barrier.cluster.wait.aligned;"   ::: "memory");

    const float* gxbase = g_gx + ((size_t)cell * LL * BB + (b0 + pb)) * G4 + jglob;
    float gxr[4];
#pragma unroll
    for (int gi = 0; gi < 4; gi++)
        gxr[gi] = gxbase[gi * HH];

    const uint32_t* hhi_base = &hp_hi[0][0][0];
    const uint32_t* hlo_base = &hp_lo[0][0][0];

    int buf = 0;
    for (int t = 0; t < LL; t++) {
        float cfr[4] = {0.0f, 0.0f, 0.0f, 0.0f};
        const int fb = buf * TB * 68 + gid * 68;
#pragma unroll
        for (int kt = 0; kt < 8; kt++) {
            int pidx = fb + kt * 8 + tig;
            uint32_t bh0 = hhi_base[pidx];
            uint32_t bh1 = hhi_base[pidx + 4];
            uint32_t bl0 = hlo_base[pidx];
            uint32_t bl1 = hlo_base[pidx + 4];
            mma16816(cfr, a_hi[kt], bh0, bh1);
            mma16816(cfr, a_hi[kt], bl0, bl1);
            mma16816(cfr, a_lo[kt], bh0, bh1);
        }
        *reinterpret_cast<float2*>(&gates_s[rloc0][2 * tig]) =
            make_float2(cfr[0], cfr[1]);
        *reinterpret_cast<float2*>(&gates_s[rloc1][2 * tig]) =
            make_float2(cfr[2], cfr[3]);
        __syncthreads();

        float gi_ = gates_s[pj][pb]       + gxr[0];
        float gf_ = gates_s[32 + pj][pb]  + gxr[1];
        float gg_ = gates_s[64 + pj][pb]  + gxr[2];
        float go_ = gates_s[96 + pj][pb]  + gxr[3];
        float ig = sigm(gi_);
        float fg = sigm(gf_);
        float gv = tanha(gg_);
        float og = sigm(go_);
        c_reg = fg * c_reg + ig * gv;
        float hv = og * tanha(c_reg);

        __nv_bfloat16 hhi = __float2bfloat16(hv);
        __nv_bfloat16 hlo = __float2bfloat16(hv - __bfloat162float(hhi));
        uint16_t hhi_b = __bfloat16_as_ushort(hhi);
        uint16_t hlo_b = __bfloat16_as_ushort(hlo);

        const int nb = buf ^ 1;
        const uint32_t ahh = nb ? hhi_u16_1 : hhi_u16_0;
        const uint32_t ahl = nb ? hlo_u16_1 : hlo_u16_0;
        asm volatile("st.shared.b16 [%0], %1;" :: "r"(ahh), "h"(hhi_b) : "memory");
        asm volatile("st.shared.b16 [%0], %1;" :: "r"(ahl), "h"(hlo_b) : "memory");
#pragma unroll
        for (int r = 1; r < 4; r++) {
            st_remote_b16(ahh, (rank + r) & 3u, hhi_b);
            st_remote_b16(ahl, (rank + r) & 3u, hlo_b);
        }
        hg[(size_t)t * HH] = hv;

        if (t + 1 < LL) {
            const float* gp = gxbase + (size_t)(t + 1) * BB * G4;
#pragma unroll
            for (int gi2 = 0; gi2 < 4; gi2++)
                gxr[gi2] = gp[gi2 * HH];
        }

        asm volatile("barrier.cluster.arrive.aligned;" ::: "memory");
        asm volatile("barrier.cluster.wait.aligned;"   ::: "memory");
        buf = nb;
    }
}

// ---------------------------------------------------------------------------
// Phase 3: y[b][t] = W_ffn . [h_h(b,t); h_f(b,t)] + b_ffn  (R9 version)
// ---------------------------------------------------------------------------
__global__ __launch_bounds__(256) void k_finalize(float* __restrict__ out,
                                                  const float* __restrict__ Wffn,
                                                  const float* __restrict__ bffn) {
    __shared__ float wf[2 * HH];
    const int b = blockIdx.x >> 1;
    const int t = (blockIdx.x & 1) * 256 + threadIdx.x;
    wf[threadIdx.x] = Wffn[threadIdx.x];
    __syncthreads();
    const float bias = bffn[0];

    const float4* p0 = reinterpret_cast<const float4*>(
        g_h + (((size_t)0 * BB + b) * LL + t) * HH);
    const float4* p1 = reinterpret_cast<const float4*>(
        g_h + (((size_t)1 * BB + b) * LL + t) * HH);
    float acc = bias;
#pragma unroll 8
    for (int q = 0; q < 32; q++) {
        float4 a = p0[q];
        acc += a.x * wf[4 * q] + a.y * wf[4 * q + 1]
             + a.z * wf[4 * q + 2] + a.w * wf[4 * q + 3];
    }
#pragma unroll 8
    for (int q = 0; q < 32; q++) {
        float4 a = p1[q];
        acc += a.x * wf[128 + 4 * q] + a.y * wf[128 + 4 * q + 1]
             + a.z * wf[128 + 4 * q + 2] + a.w * wf[128 + 4 * q + 3];
    }
    out[(size_t)b * LL + t] = acc;
}

// ---------------------------------------------------------------------------
extern "C" void kernel_launch(void* const* d_in, const int* in_sizes, int n_in,
                              void* d_out, int out_size) {
    const float* hist  = (const float*)d_in[0];
    const float* fut   = (const float*)d_in[1];
    const float* Wih_h = (const float*)d_in[2];
    const float* Whh_h = (const float*)d_in[3];
    const float* bih_h = (const float*)d_in[4];
    const float* bhh_h = (const float*)d_in[5];
    const float* Wih_f = (const float*)d_in[6];
    const float* Whh_f = (const float*)d_in[7];
    const float* bih_f = (const float*)d_in[8];
    const float* bhh_f = (const float*)d_in[9];
    const float* Wffn  = (const float*)d_in[10];
    const float* bffn  = (const float*)d_in[11];
    float* out = (float*)d_out;

    static int smem_set = 0;
    if (!smem_set) {
        cudaFuncSetAttribute(k_mma_gemm,
                             cudaFuncAttributeMaxDynamicSharedMemorySize, SMEM_P1);
        smem_set = 1;
    }

    k_convert_w<<<(2 * G4 * 32) / 256, 256>>>(Wih_h, Wih_f);

    dim3 gg(G4 / 256, (2 * MROWS) / 64);   // (2, 4096)
    k_mma_gemm<<<gg, 256, SMEM_P1>>>(hist, fut, bih_h, bhh_h, bih_f, bhh_f);

    k_recurrent<<<256, 256>>>(Whh_h, Whh_f);

    k_finalize<<<2 * BB, 256>>>(out, Wffn, bffn);
}

// round 16
// speedup vs baseline: 1.3026x; 1.2600x over previous
#include <cuda_runtime.h>
#include <cuda_bf16.h>
#include <cstdint>
#include <cstddef>

#define BB   256
#define LL   512
#define EE   256
#define HH   128
#define G4   512
#define TB   8
#define MROWS 131072          // L*B rows per cell
#define WKT  512              // W' width: [hi(256) | lo(256)]

// ---------------------------------------------------------------------------
// Device scratch
// ---------------------------------------------------------------------------
__device__ float g_gx[(size_t)2 * LL * BB * G4];            // 512 MB gates
__device__ __nv_bfloat16 g_wp[(size_t)2 * G4 * WKT];        // 1 MB W' (hi|lo)
__device__ float g_h[(size_t)2 * BB * LL * HH];             // 128 MB hidden states

// ---------------------------------------------------------------------------
// Helpers
// ---------------------------------------------------------------------------
static __device__ __forceinline__ uint32_t smem_u32(const void* p) {
    uint32_t a;
    asm("{ .reg .u64 t; cvta.to.shared.u64 t, %1; cvt.u32.u64 %0, t; }"
        : "=r"(a) : "l"(p));
    return a;
}
// st.async b32: remote smem store + remote mbarrier complete_tx (4 bytes)
static __device__ __forceinline__ void st_async_b32(uint32_t laddr, uint32_t lmbar,
                                                    uint32_t peer, uint32_t v) {
    asm volatile(
        "{ .reg .b32 ra, rm;\n\t"
        "mapa.shared::cluster.u32 ra, %0, %2;\n\t"
        "mapa.shared::cluster.u32 rm, %1, %2;\n\t"
        "st.async.shared::cluster.mbarrier::complete_tx::bytes.b32 [ra], %3, [rm]; }"
        :: "r"(laddr), "r"(lmbar), "r"(peer), "r"(v) : "memory");
}
// mbarrier ops
#define MBAR_INIT(a, c) \
    asm volatile("mbarrier.init.shared.b64 [%0], %1;" :: "r"(a), "r"((uint32_t)(c)) : "memory")
#define MBAR_EXPECT(a, tx) \
    asm volatile("mbarrier.arrive.expect_tx.shared.b64 _, [%0], %1;" \
                 :: "r"(a), "r"((uint32_t)(tx)) : "memory")
#define MBAR_WAIT(a, ph) do {                                                        \
    uint32_t _m = (a); uint32_t _p = (ph); uint32_t _d;                              \
    asm volatile("{ .reg .pred p; mbarrier.try_wait.parity.acquire.cta.shared::cta.b64 p, [%1], %2;" \
                 " selp.b32 %0,1,0,p; }" : "=r"(_d) : "r"(_m), "r"(_p) : "memory");  \
    if (!_d) {                                                                       \
        asm volatile("{ .reg .pred P1; WL%=: mbarrier.try_wait.parity.acquire.cta.shared::cta.b64 P1, [%0], %1, 0x989680;" \
                     " @P1 bra.uni WD%=; bra.uni WL%=; WD%=: }"                      \
                     :: "r"(_m), "r"(_p) : "memory");                                \
    } } while (0)
// fast activations (ex2/rcp approx)
static __device__ __forceinline__ float sigm(float x) {
    float t;
    asm("mul.f32 %0, %1, 0fBFB8AA3B;" : "=f"(t) : "f"(x));   // -x*log2(e)
    asm("ex2.approx.f32 %0, %0;" : "+f"(t));
    float r = t + 1.0f;
    asm("rcp.approx.f32 %0, %0;" : "+f"(r));
    return r;
}
static __device__ __forceinline__ float tanha(float x) {
    x = fminf(fmaxf(x, -9.0f), 9.0f);
    float t;
    asm("mul.f32 %0, %1, 0f4038AA3B;" : "=f"(t) : "f"(x));   // 2x*log2(e)
    asm("ex2.approx.f32 %0, %0;" : "+f"(t));                  // e^{2x}
    float den = t + 1.0f;
    asm("rcp.approx.f32 %0, %0;" : "+f"(den));
    return (t - 1.0f) * den;
}
// cp.async
static __device__ __forceinline__ void cp16(uint32_t dst, const void* src) {
    asm volatile("cp.async.cg.shared.global [%0], [%1], 16;"
                 :: "r"(dst), "l"(src) : "memory");
}
static __device__ __forceinline__ void cp_commit() {
    asm volatile("cp.async.commit_group;" ::: "memory");
}
template <int N>
static __device__ __forceinline__ void cp_wait() {
    asm volatile("cp.async.wait_group %0;" :: "n"(N) : "memory");
}
// ldmatrix x4 (b16)
static __device__ __forceinline__ void ldx4(uint32_t* r, uint32_t addr) {
    asm volatile("ldmatrix.sync.aligned.m8n8.x4.shared.b16 {%0,%1,%2,%3}, [%4];"
                 : "=r"(r[0]), "=r"(r[1]), "=r"(r[2]), "=r"(r[3]) : "r"(addr));
}
// bf16 HMMA m16n8k16, fp32 accum
static __device__ __forceinline__ void mma16816(float* c, const uint32_t* a,
                                                uint32_t b0, uint32_t b1) {
    asm volatile(
        "mma.sync.aligned.m16n8k16.row.col.f32.bf16.bf16.f32 "
        "{%0,%1,%2,%3}, {%4,%5,%6,%7}, {%8,%9}, {%0,%1,%2,%3};"
        : "+f"(c[0]), "+f"(c[1]), "+f"(c[2]), "+f"(c[3])
        : "r"(a[0]), "r"(a[1]), "r"(a[2]), "r"(a[3]), "r"(b0), "r"(b1));
}
static __device__ __forceinline__ uint32_t bfpack(__nv_bfloat16 a, __nv_bfloat16 b) {
    return (uint32_t)__bfloat16_as_ushort(a) | ((uint32_t)__bfloat16_as_ushort(b) << 16);
}

// ---------------------------------------------------------------------------
// W' = [hi | lo]  (512 bf16 per row) — for phase-1 GEMM
// ---------------------------------------------------------------------------
__global__ __launch_bounds__(256) void k_convert_w(const float* __restrict__ Wh,
                                                   const float* __restrict__ Wf) {
    int i = blockIdx.x * 256 + threadIdx.x;
    int e8 = i & 31;
    int nn = i >> 5;
    int cell = nn >> 9;
    int n = nn & 511;
    const float* W = cell ? Wf : Wh;
    const float4* src = reinterpret_cast<const float4*>(W + (size_t)n * EE + e8 * 8);
    float4 v0 = src[0], v1 = src[1];
    float x[8] = {v0.x, v0.y, v0.z, v0.w, v1.x, v1.y, v1.z, v1.w};
    __nv_bfloat16 hi[8], lo[8];
#pragma unroll
    for (int j = 0; j < 8; j++) {
        hi[j] = __float2bfloat16(x[j]);
        lo[j] = __float2bfloat16(x[j] - __bfloat162float(hi[j]));
    }
    uint4 ph, pl;
    ph.x = bfpack(hi[0], hi[1]); ph.y = bfpack(hi[2], hi[3]);
    ph.z = bfpack(hi[4], hi[5]); ph.w = bfpack(hi[6], hi[7]);
    pl.x = bfpack(lo[0], lo[1]); pl.y = bfpack(lo[2], lo[3]);
    pl.z = bfpack(lo[4], lo[5]); pl.w = bfpack(lo[6], lo[7]);
    __nv_bfloat16* dst = g_wp + (size_t)nn * WKT + e8 * 8;
    *reinterpret_cast<uint4*>(dst)       = ph;
    *reinterpret_cast<uint4*>(dst + 256) = pl;
}

// ---------------------------------------------------------------------------
// Phase 1 fused GEMM — EXACT R15 version (pipelined A-convert, 2 CTAs/SM).
// ---------------------------------------------------------------------------
#define OFF_B   20480
#define OFF_BIAS 102400
#define SMEM_P1 (102400 + 1024)

__global__ __launch_bounds__(256, 2) void k_mma_gemm(
    const float* __restrict__ Xh, const float* __restrict__ Xf,
    const float* __restrict__ bih_h, const float* __restrict__ bhh_h,
    const float* __restrict__ bih_f, const float* __restrict__ bhh_f)
{
    extern __shared__ __align__(16) char smem[];
    const uint32_t sbase = smem_u32(smem);
    float* bias_s = reinterpret_cast<float*>(smem + OFF_BIAS);

    const int tid  = threadIdx.x;
    const int wid  = tid >> 5;
    const int lane = tid & 31;
    const int n0 = blockIdx.x * 256;
    const int m0 = blockIdx.y * 64;
    const int cell = m0 >> 17;

    {
        const float* bi = cell ? bih_f : bih_h;
        const float* bh = cell ? bhh_f : bhh_h;
        bias_s[tid] = bi[n0 + tid] + bh[n0 + tid];
    }

    const float* X = cell ? Xf : Xh;

    const int arow = tid >> 2;
    const int aq   = (tid & 3) * 8;
    const int rA = (m0 + arow) & (MROWS - 1);
    const float* xsrc = X + (((size_t)(rA & 255)) * LL + (rA >> 8)) * EE + aq;
    const uint32_t a_sts_h = sbase + arow * 80 + aq * 2;
    const uint32_t a_sts_l = a_sts_h + 5120;

    const int warp_m = wid & 1;
    const int warp_n = wid >> 1;
    uint32_t a_off[2];
#pragma unroll
    for (int im = 0; im < 2; im++)
        a_off[im] = (warp_m * 32 + im * 16 + (lane & 15)) * 80 + (lane >> 4) * 16;
    uint32_t b_off[4];
#pragma unroll
    for (int ip = 0; ip < 4; ip++)
        b_off[ip] = (warp_n * 64 + ip * 16 + (lane >> 4) * 8 + (lane & 7)) * 80
                  + ((lane >> 3) & 1) * 16;

    float acc[2][8][4];
#pragma unroll
    for (int im = 0; im < 2; im++)
#pragma unroll
        for (int in = 0; in < 8; in++)
#pragma unroll
            for (int q = 0; q < 4; q++) acc[im][in][q] = 0.0f;

#define LOAD_B(chunk)                                                          \
    do {                                                                       \
        const int _k0 = (chunk) * 32;                                          \
        const uint32_t _bb = sbase + OFF_B + (uint32_t)((chunk) & 1) * 40960;  \
        _Pragma("unroll")                                                      \
        for (int _i = 0; _i < 8; _i++) {                                       \
            int _idx = tid + _i * 256;                                         \
            int _half = _idx >> 10;                                            \
            int _r2 = _idx & 1023;                                             \
            int _brow = _r2 >> 2;                                              \
            int _pc = _r2 & 3;                                                 \
            cp16(_bb + _half * 20480 + _brow * 80 + _pc * 16,                  \
                 g_wp + ((size_t)cell * G4 + n0 + _brow) * WKT                 \
                      + _half * 256 + _k0 + _pc * 8);                          \
        }                                                                      \
        cp_commit();                                                           \
    } while (0)

#define CONVERT_STS(dstoff)                                                    \
    do {                                                                       \
        float x8[8] = {xr0.x, xr0.y, xr0.z, xr0.w, xr1.x, xr1.y, xr1.z, xr1.w};\
        __nv_bfloat16 hi[8], lo[8];                                            \
        _Pragma("unroll")                                                      \
        for (int _j = 0; _j < 8; _j++) {                                       \
            hi[_j] = __float2bfloat16(x8[_j]);                                 \
            lo[_j] = __float2bfloat16(x8[_j] - __bfloat162float(hi[_j]));      \
        }                                                                      \
        uint4 ph, pl;                                                          \
        ph.x = bfpack(hi[0], hi[1]); ph.y = bfpack(hi[2], hi[3]);              \
        ph.z = bfpack(hi[4], hi[5]); ph.w = bfpack(hi[6], hi[7]);              \
        pl.x = bfpack(lo[0], lo[1]); pl.y = bfpack(lo[2], lo[3]);              \
        pl.z = bfpack(lo[4], lo[5]); pl.w = bfpack(lo[6], lo[7]);              \
        asm volatile("st.shared.v4.b32 [%0], {%1,%2,%3,%4};"                   \
                     :: "r"(a_sts_h + (dstoff)), "r"(ph.x), "r"(ph.y),         \
                        "r"(ph.z), "r"(ph.w) : "memory");                      \
        asm volatile("st.shared.v4.b32 [%0], {%1,%2,%3,%4};"                   \
                     :: "r"(a_sts_l + (dstoff)), "r"(pl.x), "r"(pl.y),         \
                        "r"(pl.z), "r"(pl.w) : "memory");                      \
    } while (0)

    float4 xr0 = reinterpret_cast<const float4*>(xsrc)[0];
    float4 xr1 = reinterpret_cast<const float4*>(xsrc)[1];
    LOAD_B(0);
    CONVERT_STS(0u);
    xr0 = reinterpret_cast<const float4*>(xsrc + 32)[0];
    xr1 = reinterpret_cast<const float4*>(xsrc + 32)[1];
    cp_wait<0>();
    __syncthreads();

    for (int k = 0; k < 8; ++k) {
        const uint32_t aboff = (uint32_t)(k & 1) * 10240;
        const uint32_t bboff = (uint32_t)(k & 1) * 40960;

        if (k < 7) LOAD_B(k + 1);

#pragma unroll
        for (int ks = 0; ks < 2; ks++) {
            const uint32_t kb = ks * 32;
            uint32_t ahi[2][4], bfr[16];
            ldx4(ahi[0], sbase + aboff + a_off[0] + kb);
            ldx4(ahi[1], sbase + aboff + a_off[1] + kb);
#pragma unroll
            for (int ip = 0; ip < 4; ip++)
                ldx4(bfr + ip * 4, sbase + OFF_B + bboff + b_off[ip] + kb);
#pragma unroll
            for (int im = 0; im < 2; im++)
#pragma unroll
                for (int in = 0; in < 8; in++)
                    mma16816(acc[im][in], ahi[im], bfr[in * 2], bfr[in * 2 + 1]);
            {
                uint32_t alo[2][4];
                ldx4(alo[0], sbase + aboff + 5120 + a_off[0] + kb);
                ldx4(alo[1], sbase + aboff + 5120 + a_off[1] + kb);
#pragma unroll
                for (int im = 0; im < 2; im++)
#pragma unroll
                    for (int in = 0; in < 8; in++)
                        mma16816(acc[im][in], alo[im], bfr[in * 2], bfr[in * 2 + 1]);
            }
#pragma unroll
            for (int ip = 0; ip < 4; ip++)
                ldx4(bfr + ip * 4, sbase + OFF_B + bboff + 20480 + b_off[ip] + kb);
#pragma unroll
            for (int im = 0; im < 2; im++)
#pragma unroll
                for (int in = 0; in < 8; in++)
                    mma16816(acc[im][in], ahi[im], bfr[in * 2], bfr[in * 2 + 1]);
        }

        if (k < 7) {
            CONVERT_STS((uint32_t)((k + 1) & 1) * 10240);
            if (k < 6) {
                xr0 = reinterpret_cast<const float4*>(xsrc + (k + 2) * 32)[0];
                xr1 = reinterpret_cast<const float4*>(xsrc + (k + 2) * 32)[1];
            }
            cp_wait<0>();
        }
        __syncthreads();
    }

#pragma unroll
    for (int im = 0; im < 2; im++) {
#pragma unroll
        for (int h = 0; h < 2; h++) {
            int m = m0 + warp_m * 32 + im * 16 + h * 8 + (lane >> 2);
            int r = m & (MROWS - 1);
            int t = r >> 8, b = r & 255;
            float* gp = g_gx + (((size_t)cell * LL + t) * BB + b) * G4 + n0;
#pragma unroll
            for (int in = 0; in < 8; in++) {
                int col = warp_n * 64 + in * 8 + (lane & 3) * 2;
                float2 v;
                v.x = acc[im][in][2 * h + 0] + bias_s[col];
                v.y = acc[im][in][2 * h + 1] + bias_s[col + 1];
                *reinterpret_cast<float2*>(gp + col) = v;
            }
        }
    }
}

// ---------------------------------------------------------------------------
// Phase 2: recurrent LSTM — R11 structure; ONLY the per-step cluster barrier
// is replaced by st.async.b32 broadcast + two alternating mbarriers
// (stage = t&1, parity = (t>>1)&1; full-step margin between rearm and reuse).
// Adjacent lanes pair via shfl.xor(1): even lanes store packed hi-pairs,
// odd lanes packed lo-pairs (3 remote st.async each, 1 local b32).
// ---------------------------------------------------------------------------
__global__ __launch_bounds__(256, 2) __cluster_dims__(4, 1, 1)
void k_recurrent(const float* __restrict__ Whh_h,
                 const float* __restrict__ Whh_f)
{
    __shared__ uint32_t hp_hi[2][TB][68];    // [buf][batch][k-pair] bf16x2
    __shared__ uint32_t hp_lo[2][TB][68];
    __shared__ float gates_s[128][10];
    __shared__ __align__(8) uint64_t mbx[2];

    const int tid = threadIdx.x;
    uint32_t rank;
    asm("mov.u32 %0, %%cluster_ctarank;" : "=r"(rank));
    const int q    = blockIdx.x >> 2;
    const int cell = q >> 5;
    const int b0   = (q & 31) * TB;

    const float* W = cell ? Whh_f : Whh_h;

    const int w    = tid >> 5;
    const int lane = tid & 31;
    const int gid  = lane >> 2;             // 0..7
    const int tig  = lane & 3;              // 0..3

    const int rloc0 = w * 16 + gid;
    const int rloc1 = rloc0 + 8;
    const int ng0 = (rloc0 >> 5) * HH + (int)rank * 32 + (rloc0 & 31);
    const int ng1 = (rloc1 >> 5) * HH + (int)rank * 32 + (rloc1 & 31);

    uint32_t a_hi[8][4], a_lo[8][4];
#pragma unroll
    for (int kt = 0; kt < 8; kt++) {
        int c0 = kt * 16 + 2 * tig;
#pragma unroll
        for (int rr = 0; rr < 2; rr++) {
            const float* wr = W + (size_t)(rr ? ng1 : ng0) * HH;
#pragma unroll
            for (int cc = 0; cc < 2; cc++) {
                float xa = wr[c0 + cc * 8];
                float xb = wr[c0 + cc * 8 + 1];
                __nv_bfloat16 ha = __float2bfloat16(xa);
                __nv_bfloat16 hb = __float2bfloat16(xb);
                __nv_bfloat16 la = __float2bfloat16(xa - __bfloat162float(ha));
                __nv_bfloat16 lb = __float2bfloat16(xb - __bfloat162float(hb));
                a_hi[kt][cc * 2 + rr] = bfpack(ha, hb);
                a_lo[kt][cc * 2 + rr] = bfpack(la, lb);
            }
        }
    }

    const int pb = tid >> 5;
    const int pj = tid & 31;
    const int jglob = (int)rank * 32 + pj;
    // pair store address (4B-aligned; unit pair = jglob & ~1)
    const int is_odd = pj & 1;
    const uint32_t pair_byte = (uint32_t)(pb * 136 + (jglob & ~1)) * 2;
    const uint32_t parr0 = (is_odd ? smem_u32(&hp_lo[0][0][0])
                                   : smem_u32(&hp_hi[0][0][0])) + pair_byte;
    const uint32_t parr1 = (is_odd ? smem_u32(&hp_lo[1][0][0])
                                   : smem_u32(&hp_hi[1][0][0])) + pair_byte;
    const uint32_t mb0 = smem_u32(&mbx[0]);
    const uint32_t mb1 = smem_u32(&mbx[1]);
    float* hg = g_h + (((size_t)cell * BB + b0 + pb) * LL) * HH + jglob;

    for (int i = tid; i < 2 * TB * 68; i += 256) {
        (&hp_hi[0][0][0])[i] = 0u;
        (&hp_lo[0][0][0])[i] = 0u;
    }
    float c_reg = 0.0f;
    if (tid == 0) { MBAR_INIT(mb0, 1); MBAR_INIT(mb1, 1); }
    __syncthreads();
    asm volatile("barrier.cluster.arrive.aligned;" ::: "memory");
    asm volatile("barrier.cluster.wait.aligned;"   ::: "memory");
    if (tid == 0) { MBAR_EXPECT(mb0, 3072); MBAR_EXPECT(mb1, 3072); }
    __syncthreads();

    const float* gxbase = g_gx + ((size_t)cell * LL * BB + (b0 + pb)) * G4 + jglob;
    float gxr[4];
#pragma unroll
    for (int gi = 0; gi < 4; gi++)
        gxr[gi] = gxbase[gi * HH];

    const uint32_t* hhi_base = &hp_hi[0][0][0];
    const uint32_t* hlo_base = &hp_lo[0][0][0];

    int buf = 0;
    for (int t = 0; t < LL; t++) {
        float cfr[4] = {0.0f, 0.0f, 0.0f, 0.0f};
        const int fb = buf * TB * 68 + gid * 68;
#pragma unroll
        for (int kt = 0; kt < 8; kt++) {
            int pidx = fb + kt * 8 + tig;
            uint32_t bh0 = hhi_base[pidx];
            uint32_t bh1 = hhi_base[pidx + 4];
            uint32_t bl0 = hlo_base[pidx];
            uint32_t bl1 = hlo_base[pidx + 4];
            mma16816(cfr, a_hi[kt], bh0, bh1);
            mma16816(cfr, a_hi[kt], bl0, bl1);
            mma16816(cfr, a_lo[kt], bh0, bh1);
        }
        *reinterpret_cast<float2*>(&gates_s[rloc0][2 * tig]) =
            make_float2(cfr[0], cfr[1]);
        *reinterpret_cast<float2*>(&gates_s[rloc1][2 * tig]) =
            make_float2(cfr[2], cfr[3]);
        __syncthreads();

        float gi_ = gates_s[pj][pb]       + gxr[0];
        float gf_ = gates_s[32 + pj][pb]  + gxr[1];
        float gg_ = gates_s[64 + pj][pb]  + gxr[2];
        float go_ = gates_s[96 + pj][pb]  + gxr[3];
        float ig = sigm(gi_);
        float fg = sigm(gf_);
        float gv = tanha(gg_);
        float og = sigm(go_);
        c_reg = fg * c_reg + ig * gv;
        float hv = og * tanha(c_reg);

        __nv_bfloat16 hhi = __float2bfloat16(hv);
        __nv_bfloat16 hlo = __float2bfloat16(hv - __bfloat162float(hhi));
        uint32_t combo = (uint32_t)__bfloat16_as_ushort(hhi)
                       | ((uint32_t)__bfloat16_as_ushort(hlo) << 16);
        uint32_t pcombo = __shfl_xor_sync(0xffffffffu, combo, 1);
        // even lane: hi-pair (units j, j+1); odd lane: lo-pair (units j-1, j)
        uint32_t pairv = is_odd ? ((pcombo >> 16) | (combo & 0xFFFF0000u))
                                : ((combo & 0xFFFFu) | (pcombo << 16));

        const int nb = buf ^ 1;
        const uint32_t pa = nb ? parr1 : parr0;
        const uint32_t mbs = (t & 1) ? mb1 : mb0;
        asm volatile("st.shared.b32 [%0], %1;" :: "r"(pa), "r"(pairv) : "memory");
#pragma unroll
        for (int r = 1; r < 4; r++)
            st_async_b32(pa, mbs, (rank + r) & 3u, pairv);
        hg[(size_t)t * HH] = hv;

        if (t + 1 < LL) {
            const float* gp = gxbase + (size_t)(t + 1) * BB * G4;
#pragma unroll
            for (int gi2 = 0; gi2 < 4; gi2++)
                gxr[gi2] = gp[gi2 * HH];
        }

        // wait for peers' step-t pairs (stage barrier, 2-step ring)
        MBAR_WAIT(mbs, (uint32_t)((t >> 1) & 1));
        if (tid == 0) MBAR_EXPECT(mbs, 3072);
        __syncthreads();
        buf = nb;
    }

    asm volatile("barrier.cluster.arrive.aligned;" ::: "memory");
    asm volatile("barrier.cluster.wait.aligned;"   ::: "memory");
}

// ---------------------------------------------------------------------------
// Phase 3: y[b][t] = W_ffn . [h_h(b,t); h_f(b,t)] + b_ffn  (R9 version)
// ---------------------------------------------------------------------------
__global__ __launch_bounds__(256) void k_finalize(float* __restrict__ out,
                                                  const float* __restrict__ Wffn,
                                                  const float* __restrict__ bffn) {
    __shared__ float wf[2 * HH];
    const int b = blockIdx.x >> 1;
    const int t = (blockIdx.x & 1) * 256 + threadIdx.x;
    wf[threadIdx.x] = Wffn[threadIdx.x];
    __syncthreads();
    const float bias = bffn[0];

    const float4* p0 = reinterpret_cast<const float4*>(
        g_h + (((size_t)0 * BB + b) * LL + t) * HH);
    const float4* p1 = reinterpret_cast<const float4*>(
        g_h + (((size_t)1 * BB + b) * LL + t) * HH);
    float acc = bias;
#pragma unroll 8
    for (int q = 0; q < 32; q++) {
        float4 a = p0[q];
        acc += a.x * wf[4 * q] + a.y * wf[4 * q + 1]
             + a.z * wf[4 * q + 2] + a.w * wf[4 * q + 3];
    }
#pragma unroll 8
    for (int q = 0; q < 32; q++) {
        float4 a = p1[q];
        acc += a.x * wf[128 + 4 * q] + a.y * wf[128 + 4 * q + 1]
             + a.z * wf[128 + 4 * q + 2] + a.w * wf[128 + 4 * q + 3];
    }
    out[(size_t)b * LL + t] = acc;
}

// ---------------------------------------------------------------------------
extern "C" void kernel_launch(void* const* d_in, const int* in_sizes, int n_in,
                              void* d_out, int out_size) {
    const float* hist  = (const float*)d_in[0];
    const float* fut   = (const float*)d_in[1];
    const float* Wih_h = (const float*)d_in[2];
    const float* Whh_h = (const float*)d_in[3];
    const float* bih_h = (const float*)d_in[4];
    const float* bhh_h = (const float*)d_in[5];
    const float* Wih_f = (const float*)d_in[6];
    const float* Whh_f = (const float*)d_in[7];
    const float* bih_f = (const float*)d_in[8];
    const float* bhh_f = (const float*)d_in[9];
    const float* Wffn  = (const float*)d_in[10];
    const float* bffn  = (const float*)d_in[11];
    float* out = (float*)d_out;

    static int smem_set = 0;
    if (!smem_set) {
        cudaFuncSetAttribute(k_mma_gemm,
                             cudaFuncAttributeMaxDynamicSharedMemorySize, SMEM_P1);
        smem_set = 1;
    }

    k_convert_w<<<(2 * G4 * 32) / 256, 256>>>(Wih_h, Wih_f);

    dim3 gg(G4 / 256, (2 * MROWS) / 64);   // (2, 4096)
    k_mma_gemm<<<gg, 256, SMEM_P1>>>(hist, fut, bih_h, bhh_h, bih_f, bhh_f);

    k_recurrent<<<256, 256>>>(Whh_h, Whh_f);

    k_finalize<<<2 * BB, 256>>>(out, Wffn, bffn);
}